// round 6
// baseline (speedup 1.0000x reference)
#include <cuda_runtime.h>
#include <math.h>

#define BATCH 128
#define NDIM 512
#define POWER_ITERS 10
#define N_ITERS 500
#define NTHREADS 1024
#define NWARPS 32
#define NTILES 136              // 16*17/2 upper-triangular 32x32 tiles
#define TILE_ELEMS 1024
#define INST_STRIDE (NTILES * TILE_ELEMS)   // 544 KB per instance

// dynamic smem layout (floats)
#define ACC_OFF   0                              // 32 x 512   (64 KB)
#define STAGE_OFF (NWARPS * NDIM)                // 32 x 1152  (144 KB)
#define SY_OFF    (STAGE_OFF + NWARPS * 1152)
#define SV_OFF    (SY_OFF + NDIM)
#define SW_OFF    (SV_OFF + NDIM)
#define DSM_FLOATS (SW_OFF + NDIM)
#define DSM_BYTES (DSM_FLOATS * 4)               // 219,136 B

// Packed symmetric Sigma: 128 * 544KB = 68 MB (L2-resident)
__device__ float g_pack[(size_t)BATCH * INST_STRIDE];

// ---------------------------------------------------------------------------
// Kernel 1: symmetrize + pack upper triangle.
// Layout: P[k*128 + c*4 + j] = T[4k+j][c],  T = 0.5(S_IJ + S_JI^T)
// ---------------------------------------------------------------------------
__global__ void pack_kernel(const float* __restrict__ Sigma) {
    __shared__ float sA[32][33];
    __shared__ float sB[32][33];
    const int t = blockIdx.x;
    const int b = blockIdx.y;
    int I = 0, rem = t;
    while (rem >= 16 - I) { rem -= 16 - I; ++I; }
    const int J = I + rem;

    const float* S = Sigma + (size_t)b * NDIM * NDIM;
    float* P = g_pack + (size_t)b * INST_STRIDE + (size_t)t * TILE_ELEMS;
    const int tx = threadIdx.x, ty = threadIdx.y;
    const int tid = ty * 32 + tx;

    #pragma unroll
    for (int r = ty; r < 32; r += 8) {
        sA[r][tx] = S[(size_t)(I * 32 + r) * NDIM + J * 32 + tx];
        sB[r][tx] = S[(size_t)(J * 32 + r) * NDIM + I * 32 + tx];
    }
    __syncthreads();

    #pragma unroll
    for (int q = 0; q < 4; ++q) {
        const int addr = tid + (q << 8);
        const int k = addr >> 7;
        const int c = (addr >> 2) & 31;
        const int j = addr & 3;
        const int r = (k << 2) + j;
        P[addr] = 0.5f * (sA[r][c] + sB[c][r]);   // T[r][c]
    }
}

// ---------------------------------------------------------------------------
// reductions
// ---------------------------------------------------------------------------
__device__ __forceinline__ float warp_sum(float v) {
    #pragma unroll
    for (int o = 16; o; o >>= 1) v += __shfl_xor_sync(0xffffffffu, v, o);
    return v;
}
__device__ __forceinline__ float warp_max(float v) {
    #pragma unroll
    for (int o = 16; o; o >>= 1) v = fmaxf(v, __shfl_xor_sync(0xffffffffu, v, o));
    return v;
}
__device__ __forceinline__ float block_sum(float v, volatile float* red,
                                           int lane, int wid) {
    v = warp_sum(v);
    __syncthreads();
    if (lane == 0) red[wid] = v;
    __syncthreads();
    float x = red[lane];            // 32 warps -> all 32 lanes valid
    return warp_sum(x);
}

// ---------------------------------------------------------------------------
// Symmetric matvec, staged two-pass per tile. Direct LDG consumption
// (latency hidden by 8 warps/SMSP). Returns (Ssym*y)[tid] for tid<512, 0 else.
// ---------------------------------------------------------------------------
__device__ __forceinline__ float matvec_sym(const float* __restrict__ P,
                                            const float* __restrict__ sy,
                                            float* __restrict__ accAll,
                                            float* __restrict__ stageAll,
                                            const int* __restrict__ tI,
                                            const int* __restrict__ tJ,
                                            int tid, int lane, int wid) {
    float* acc = accAll + (wid << 9);
    {
        const float4 z = make_float4(0.f, 0.f, 0.f, 0.f);
        float4* a4 = (float4*)acc;
        a4[lane] = z; a4[lane + 32] = z; a4[lane + 64] = z; a4[lane + 96] = z;
    }
    float* stg = stageAll + wid * 1152;

    for (int t = wid; t < NTILES; t += NWARPS) {
        const float4* PT4 = (const float4*)(P + t * TILE_ELEMS);
        const int I = tI[t], J = tJ[t];
        const float4* yI4 = (const float4*)(sy + (I << 5));
        float a0 = 0.f, a1 = 0.f;
        if (I == J) {
            #pragma unroll
            for (int k = 0; k < 8; ++k) {
                const float4 e  = PT4[(k << 5) + lane];
                const float4 yb = yI4[k];
                a0 = fmaf(e.x, yb.x, a0); a1 = fmaf(e.y, yb.y, a1);
                a0 = fmaf(e.z, yb.z, a0); a1 = fmaf(e.w, yb.w, a1);
            }
            acc[(J << 5) + lane] += a0 + a1;
        } else {
            #pragma unroll
            for (int k = 0; k < 8; ++k) {
                const float4 e  = PT4[(k << 5) + lane];
                const float4 yb = yI4[k];
                a0 = fmaf(e.x, yb.x, a0); a1 = fmaf(e.y, yb.y, a1);
                a0 = fmaf(e.z, yb.z, a0); a1 = fmaf(e.w, yb.w, a1);
                stg[((k << 2) + 0) * 36 + lane] = e.x;   // conflict-free
                stg[((k << 2) + 1) * 36 + lane] = e.y;
                stg[((k << 2) + 2) * 36 + lane] = e.z;
                stg[((k << 2) + 3) * 36 + lane] = e.w;
            }
            acc[(J << 5) + lane] += a0 + a1;
            __syncwarp();
            const float4* yJ4 = (const float4*)(sy + (J << 5));
            float b0 = 0.f, b1 = 0.f;
            #pragma unroll
            for (int m = 0; m < 8; ++m) {
                const float4 s  = *(const float4*)(stg + lane * 36 + (m << 2));
                const float4 yb = yJ4[m];
                b0 = fmaf(s.x, yb.x, b0); b1 = fmaf(s.y, yb.y, b1);
                b0 = fmaf(s.z, yb.z, b0); b1 = fmaf(s.w, yb.w, b1);
            }
            acc[(I << 5) + lane] += b0 + b1;
            __syncwarp();
        }
    }
    __syncthreads();
    float s = 0.0f;
    if (tid < NDIM) {
        float s0 = 0.f, s1 = 0.f, s2 = 0.f, s3 = 0.f;
        #pragma unroll
        for (int w = 0; w < 8; ++w) {
            s0 += accAll[((4 * w + 0) << 9) + tid];
            s1 += accAll[((4 * w + 1) << 9) + tid];
            s2 += accAll[((4 * w + 2) << 9) + tid];
            s3 += accAll[((4 * w + 3) << 9) + tid];
        }
        s = (s0 + s1) + (s2 + s3);
    }
    return s;
}

// prefetch one 4KB tile into L1: each lane touches one 128B line
__device__ __forceinline__ void prefetch_tile(const float* __restrict__ P,
                                              int t, int lane) {
    const char* p = (const char*)(P + t * TILE_ELEMS) + (lane << 7);
    asm volatile("prefetch.global.L1 [%0];" :: "l"(p));
}

// ---------------------------------------------------------------------------
// Kernel 2: per-instance solver. grid=128 CTAs, block=1024 threads.
// ---------------------------------------------------------------------------
__global__ void __launch_bounds__(NTHREADS, 1)
qp_solver_kernel(const float* __restrict__ mu_g, float* __restrict__ out) {
    extern __shared__ float dsm[];
    float* accAll   = dsm + ACC_OFF;
    float* stageAll = dsm + STAGE_OFF;
    float* sy       = dsm + SY_OFF;
    float* sv       = dsm + SV_OFF;
    float* sw       = dsm + SW_OFF;
    __shared__ float red[NWARPS];
    __shared__ int   sh_tI[NTILES], sh_tJ[NTILES];
    __shared__ int   sflag;

    const int b    = blockIdx.x;
    const int tid  = threadIdx.x;
    const int lane = tid & 31;
    const int wid  = tid >> 5;
    const float* P = g_pack + (size_t)b * INST_STRIDE;
    const float invN = 1.0f / (float)NDIM;

    if (tid < NTILES) {
        int I = 0, rem = tid;
        while (rem >= 16 - I) { rem -= 16 - I; ++I; }
        sh_tI[tid] = I;
        sh_tJ[tid] = I + rem;
    }
    if (tid == 0) sflag = 0;
    const float rmu = (tid < NDIM) ? mu_g[(size_t)b * NDIM + tid] : 0.0f;
    if (tid < NDIM) sy[tid] = invN;
    __syncthreads();

    // ---- power iteration (answer is step-independent; margin below) ----
    float ry = (tid < NDIM) ? invN : 0.0f;
    for (int it = 0; it < POWER_ITERS; ++it) {
        const float gi = matvec_sym(P, sy, accAll, stageAll, sh_tI, sh_tJ,
                                    tid, lane, wid);
        const float ss = block_sum(gi * gi, red, lane, wid);
        const float inv = 1.0f / (sqrtf(ss) + 1e-12f);
        ry = gi * inv;
        if (tid < NDIM) sy[tid] = ry;        // safe: block_sum barriers passed
        __syncthreads();
    }
    const float gi0  = matvec_sym(P, sy, accAll, stageAll, sh_tI, sh_tJ,
                                  tid, lane, wid);
    const float lmax = block_sum(ry * gi0, red, lane, wid);
    const float step = 1.0f / (2.0f * lmax * 1.08f + 1e-8f);  // 8% margin

    // ---- FISTA with adaptive restart; scalar phase on warp 0 ----
    if (tid < NDIM) { sy[tid] = invN; sw[tid] = invN; }
    __syncthreads();
    float t_mom = 1.0f;                       // meaningful in warp 0 only

    for (int it = 0; it < N_ITERS; ++it) {
        const float gi = matvec_sym(P, sy, accAll, stageAll, sh_tI, sh_tJ,
                                    tid, lane, wid);
        if (tid < NDIM) sv[tid] = sy[tid] - step * (2.0f * gi - rmu);
        prefetch_tile(P, wid, lane);          // warm L1 for next matvec
        __syncthreads();                      // (B) sv ready

        if (wid == 0) {
            float vv[16];
            #pragma unroll
            for (int j = 0; j < 16; ++j) vv[j] = sv[(j << 5) + lane];

            // simplex projection: Michelot fixed point (== sort-based theta)
            float s = 0.f;
            #pragma unroll
            for (int j = 0; j < 16; ++j) s += vv[j];
            s = warp_sum(s);
            float theta = (s - 1.0f) * invN;
            #pragma unroll 1
            for (int pit = 0; pit < 40; ++pit) {
                float sa = 0.f, sc = 0.f;
                #pragma unroll
                for (int j = 0; j < 16; ++j) {
                    if (vv[j] > theta) { sa += vv[j]; sc += 1.0f; }
                }
                sa = warp_sum(sa); sc = warp_sum(sc);
                const float tn = (sa - 1.0f) / sc;
                if (tn == theta) break;       // uniform across warp
                theta = tn;
            }

            // restart test + convergence check
            float mx = 0.f, rdot = 0.f;
            #pragma unroll
            for (int j = 0; j < 16; ++j) {
                const float wo  = sw[(j << 5) + lane];
                const float yo  = sy[(j << 5) + lane];
                const float wnj = fmaxf(vv[j] - theta, 0.0f);
                mx   = fmaxf(mx, fabsf(wnj - wo));
                rdot += (yo - wnj) * (wnj - wo);
            }
            mx = warp_max(mx); rdot = warp_sum(rdot);

            float coef;
            if (rdot > 0.0f) { t_mom = 1.0f; coef = 0.0f; }
            else {
                const float tn = 0.5f * (1.0f + sqrtf(1.0f + 4.0f * t_mom * t_mom));
                coef = (t_mom - 1.0f) / tn;
                t_mom = tn;
            }
            #pragma unroll
            for (int j = 0; j < 16; ++j) {
                const float wo  = sw[(j << 5) + lane];
                const float wnj = fmaxf(vv[j] - theta, 0.0f);
                sw[(j << 5) + lane] = wnj;
                sy[(j << 5) + lane] = wnj + coef * (wnj - wo);
            }
            if (lane == 0) sflag = (mx < 1e-6f) ? 1 : 0;
        }
        __syncthreads();                      // (C) sy/sw/sflag ready
        if (sflag) break;                     // uniform
    }

    if (tid < NDIM) out[(size_t)b * NDIM + tid] = sw[tid];
}

// ---------------------------------------------------------------------------
extern "C" void kernel_launch(void* const* d_in, const int* in_sizes, int n_in,
                              void* d_out, int out_size) {
    const float* mu    = (const float*)d_in[0];   // [128, 512]
    const float* Sigma = (const float*)d_in[1];   // [128, 512, 512]
    float* out = (float*)d_out;                   // [128, 512]

    cudaFuncSetAttribute(qp_solver_kernel,
                         cudaFuncAttributeMaxDynamicSharedMemorySize, DSM_BYTES);

    dim3 gs(NTILES, BATCH);
    dim3 bs(32, 8);
    pack_kernel<<<gs, bs>>>(Sigma);
    qp_solver_kernel<<<BATCH, NTHREADS, DSM_BYTES>>>(mu, out);
}